// round 1
// baseline (speedup 1.0000x reference)
#include <cuda_runtime.h>

// CrossAttention_5385888989393 — algebraically reduced channel-attention.
//
//   G[b]    = f_m[b] (512x4096) @ f_n[b]^T            (NT GEMM, K=4096)
//   T[b,h]  = G[b] @ Wk_h^T        (512x64)           (NT GEMM, K=512)
//   dots    = (Wq_h @ T[b,h]) * scale  (64x64)        (NN GEMM, K=512)
//   attn    = softmax(dots, axis=-1)
//   U[b]    : row(h*64+i) = attn[b,h,i,:] @ Wv_h      (NN GEMM, K=64)
//   M[b]    = Wout @ U[b]          (512x512)          (NN GEMM, K=512)
//   out[b]  = M[b] @ f_n[b] + bout (512x4096)         (NN GEMM, K=512, bias)
//
// Total ~39 GFLOP fp32 (vs 73 GFLOP naive).

#define BATCH 8
#define NHEADS 8
#define DH 64
#define CDIM 512
#define NSP 4096

// Scratch (static __device__ — no allocations allowed)
__device__ float g_G[BATCH * CDIM * CDIM];            // 8 MB
__device__ float g_T[BATCH * NHEADS * CDIM * DH];     // 8 MB
__device__ float g_dots[BATCH * NHEADS * DH * DH];    // 1 MB
__device__ float g_U[BATCH * CDIM * CDIM];            // 8 MB
__device__ float g_M[BATCH * CDIM * CDIM];            // 8 MB

// ---------------------------------------------------------------------------
// Generic batched tiled SGEMM.
//   C[M,N] = alpha * A(M,K) * op(B) (+ bias[m])
//   A row-major, lda = K.
//   TRB=true : B is (N,K) row-major (contract along rows)   [NT]
//   TRB=false: B is (K,N) row-major                         [NN]
//   Batch index z = blockIdx.z -> (i1 = z / B2, i2 = z % B2); per-operand
//   strides (sX1, sX2) let A/B/C batch over different axes (b vs head).
// ---------------------------------------------------------------------------
template <int BM, int BN, int BK, int TM, int TN, bool TRB, bool BIAS>
__global__ void __launch_bounds__((BM / TM) * (BN / TN))
sgemm(const float* __restrict__ A0, const float* __restrict__ B0,
      float* __restrict__ C0, const float* __restrict__ bias,
      int M, int N, int K,
      long long sA1, long long sA2, long long sB1, long long sB2,
      long long sC1, long long sC2, int B2, float alpha)
{
    constexpr int THREADS = (BM / TM) * (BN / TN);

    int z = blockIdx.z;
    int i1 = z / B2;
    int i2 = z - i1 * B2;
    const float* A  = A0 + (size_t)i1 * sA1 + (size_t)i2 * sA2;
    const float* Bp = B0 + (size_t)i1 * sB1 + (size_t)i2 * sB2;
    float*       Cp = C0 + (size_t)i1 * sC1 + (size_t)i2 * sC2;

    __shared__ float As[BK][BM + 4];
    __shared__ float Bs[BK][BN + 4];

    const int tid = threadIdx.x;
    const int tn  = tid % (BN / TN);
    const int tm  = tid / (BN / TN);
    const int rowC = blockIdx.y * BM + tm * TM;
    const int colC = blockIdx.x * BN + tn * TN;

    float acc[TM][TN] = {};

    const int A_F4 = BM * BK / 4;
    const int B_F4 = BN * BK / 4;   // same element count either orientation

    for (int k0 = 0; k0 < K; k0 += BK) {
        // ---- A tile: BM x BK, K-contiguous; store transposed to As[k][m]
        #pragma unroll
        for (int t = tid; t < A_F4; t += THREADS) {
            int r  = t / (BK / 4);
            int c4 = (t % (BK / 4)) * 4;
            float4 v = *reinterpret_cast<const float4*>(
                A + (size_t)(blockIdx.y * BM + r) * K + k0 + c4);
            As[c4 + 0][r] = v.x; As[c4 + 1][r] = v.y;
            As[c4 + 2][r] = v.z; As[c4 + 3][r] = v.w;
        }
        // ---- B tile
        if (TRB) {
            // B (N,K) row-major: load K-contiguous, transpose to Bs[k][n]
            #pragma unroll
            for (int t = tid; t < B_F4; t += THREADS) {
                int r  = t / (BK / 4);
                int c4 = (t % (BK / 4)) * 4;
                float4 v = *reinterpret_cast<const float4*>(
                    Bp + (size_t)(blockIdx.x * BN + r) * K + k0 + c4);
                Bs[c4 + 0][r] = v.x; Bs[c4 + 1][r] = v.y;
                Bs[c4 + 2][r] = v.z; Bs[c4 + 3][r] = v.w;
            }
        } else {
            // B (K,N) row-major: N-contiguous, direct float4 into Bs[k][n]
            #pragma unroll
            for (int t = tid; t < B_F4; t += THREADS) {
                int r  = t / (BN / 4);
                int c4 = (t % (BN / 4)) * 4;
                float4 v = *reinterpret_cast<const float4*>(
                    Bp + (size_t)(k0 + r) * N + blockIdx.x * BN + c4);
                *reinterpret_cast<float4*>(&Bs[r][c4]) = v;
            }
        }
        __syncthreads();

        #pragma unroll
        for (int k = 0; k < BK; k++) {
            float ra[TM], rb[TN];
            #pragma unroll
            for (int i = 0; i < TM; i++) ra[i] = As[k][tm * TM + i];
            #pragma unroll
            for (int j = 0; j < TN; j++) rb[j] = Bs[k][tn * TN + j];
            #pragma unroll
            for (int i = 0; i < TM; i++)
                #pragma unroll
                for (int j = 0; j < TN; j++)
                    acc[i][j] = fmaf(ra[i], rb[j], acc[i][j]);
        }
        __syncthreads();
    }

    #pragma unroll
    for (int i = 0; i < TM; i++) {
        float bv = BIAS ? bias[rowC + i] : 0.0f;
        #pragma unroll
        for (int j = 0; j < TN; j++)
            Cp[(size_t)(rowC + i) * N + colC + j] = alpha * acc[i][j] + bv;
    }
}

// ---------------------------------------------------------------------------
// Softmax over rows of 64 (one warp per row), in place.
// ---------------------------------------------------------------------------
__global__ void softmax64(float* __restrict__ dots)
{
    int warp = (blockIdx.x * blockDim.x + threadIdx.x) >> 5;
    int lane = threadIdx.x & 31;
    float* row = dots + (size_t)warp * 64;

    float a = row[lane];
    float b = row[lane + 32];
    float m = fmaxf(a, b);
    #pragma unroll
    for (int o = 16; o > 0; o >>= 1) m = fmaxf(m, __shfl_xor_sync(0xffffffffu, m, o));
    float e1 = __expf(a - m);
    float e2 = __expf(b - m);
    float s = e1 + e2;
    #pragma unroll
    for (int o = 16; o > 0; o >>= 1) s += __shfl_xor_sync(0xffffffffu, s, o);
    float inv = 1.0f / s;
    row[lane]      = e1 * inv;
    row[lane + 32] = e2 * inv;
}

extern "C" void kernel_launch(void* const* d_in, const int* in_sizes, int n_in,
                              void* d_out, int out_size)
{
    const float* f_m  = (const float*)d_in[0];
    const float* f_n  = (const float*)d_in[1];
    const float* Wq   = (const float*)d_in[2];
    const float* Wkv  = (const float*)d_in[3];
    const float* Wout = (const float*)d_in[4];
    const float* bout = (const float*)d_in[5];
    float* out = (float*)d_out;

    float *G, *T, *dots, *U, *Mm;
    cudaGetSymbolAddress((void**)&G,    g_G);
    cudaGetSymbolAddress((void**)&T,    g_T);
    cudaGetSymbolAddress((void**)&dots, g_dots);
    cudaGetSymbolAddress((void**)&U,    g_U);
    cudaGetSymbolAddress((void**)&Mm,   g_M);

    const long long CF  = (long long)CDIM * NSP;     // 512*4096 per-batch feature
    const long long CC  = (long long)CDIM * CDIM;    // 512*512
    const long long THD = (long long)CDIM * DH;      // 512*64

    // 1) G[b] = f_m[b] @ f_n[b]^T   (M=512, N=512, K=4096, NT)
    sgemm<128, 128, 16, 8, 8, true, false><<<dim3(4, 4, BATCH), 256>>>(
        f_m, f_n, G, nullptr, CDIM, CDIM, NSP,
        CF, 0, CF, 0, CC, 0, 1, 1.0f);

    // 2) T[b,h] = G[b] @ Wk_h^T    (M=512, N=64, K=512, NT), z = b*8+h
    sgemm<64, 64, 16, 4, 4, true, false><<<dim3(1, 8, BATCH * NHEADS), 256>>>(
        G, Wkv, T, nullptr, CDIM, DH, CDIM,
        CC, 0, 0, (long long)DH * CDIM, (long long)NHEADS * THD, THD,
        NHEADS, 1.0f);

    // 3) dots[b,h] = (Wq_h @ T[b,h]) * scale   (M=64, N=64, K=512, NN)
    sgemm<64, 64, 16, 4, 4, false, false><<<dim3(1, 1, BATCH * NHEADS), 256>>>(
        Wq, T, dots, nullptr, DH, DH, CDIM,
        0, (long long)DH * CDIM, (long long)NHEADS * THD, THD,
        (long long)NHEADS * DH * DH, (long long)DH * DH,
        NHEADS, 0.125f);

    // 4) attn = softmax(dots)   (B*H*64 = 4096 rows of 64)
    softmax64<<<BATCH * NHEADS * DH / 8, 256>>>(dots);

    // 5) U[b] rows (h*64+i) = attn[b,h] @ Wv_h  (M=64, N=512, K=64, NN)
    sgemm<64, 64, 16, 4, 4, false, false><<<dim3(8, 1, BATCH * NHEADS), 256>>>(
        dots, Wkv + (size_t)CDIM * CDIM, U, nullptr, DH, CDIM, DH,
        (long long)NHEADS * DH * DH, (long long)DH * DH,
        0, (long long)DH * CDIM,
        CC, (long long)DH * CDIM,
        NHEADS, 1.0f);

    // 6) M[b] = Wout @ U[b]   (M=512, N=512, K=512, NN)
    sgemm<128, 128, 16, 8, 8, false, false><<<dim3(4, 4, BATCH), 256>>>(
        Wout, U, Mm, nullptr, CDIM, CDIM, CDIM,
        0, 0, CC, 0, CC, 0, 1, 1.0f);

    // 7) out[b] = M[b] @ f_n[b] + bout   (M=512, N=4096, K=512, NN, bias)
    sgemm<128, 128, 16, 8, 8, false, true><<<dim3(32, 4, BATCH), 256>>>(
        Mm, f_n, out, bout, CDIM, NSP, CDIM,
        CC, 0, CF, 0, CF, 0, 1, 1.0f);
}

// round 4
// speedup vs baseline: 1.8805x; 1.8805x over previous
#include <cuda_runtime.h>

// CrossAttention_5385888989393 — reduced channel-attention, TF32 tensor cores.
//
//   G[b]    = f_m[b] @ f_n[b]^T          (NT, K=4096)  [tf32]
//   T[b,h]  = G[b] @ Wk_h^T              (NT, K=512)   [tf32]
//   dots    = (Wq_h @ T[b,h]) * scale    (NN, K=512)   [fp32]
//   attn    = softmax(dots)
//   U[b]    = attn[b,h] @ Wv_h           (NN, K=64)    [fp32]
//   M[b]    = Wout @ U[b]                (NN, K=512)   [tf32]
//   out[b]  = M[b] @ f_n[b] + bout       (NN, K=512)   [tf32]

#define BATCH 8
#define NHEADS 8
#define DH 64
#define CDIM 512
#define NSP 4096

__device__ float g_G[BATCH * CDIM * CDIM];
__device__ float g_T[BATCH * NHEADS * CDIM * DH];
__device__ float g_dots[BATCH * NHEADS * DH * DH];
__device__ float g_U[BATCH * CDIM * CDIM];
__device__ float g_M[BATCH * CDIM * CDIM];

__device__ __forceinline__ unsigned f2tf(float f) {
    unsigned u;
    asm("cvt.rna.tf32.f32 %0, %1;" : "=r"(u) : "f"(f));
    return u;
}

// ---------------------------------------------------------------------------
// TF32 tensor-core GEMM via mma.sync.aligned.m16n8k8.row.col.f32.tf32.tf32.f32
//   C[M,N] = alpha * A(M,K) * op(B) (+ bias[m])
//   A row-major (K contiguous).
//   TRB=true : B is (N,K) row-major  [NT]
//   TRB=false: B is (K,N) row-major  [NN]
//   256 threads = 8 warps arranged WRR x WCC; warp tile (BM/WRR) x (BN/WCC).
// ---------------------------------------------------------------------------
template <int BM, int BN, int WRR, int WCC, bool TRB, bool BIAS>
__global__ void __launch_bounds__(256)
tf32gemm(const float* __restrict__ A0, const float* __restrict__ B0,
         float* __restrict__ C0, const float* __restrict__ bias,
         int M, int N, int K,
         long long sA1, long long sA2, long long sB1, long long sB2,
         long long sC1, long long sC2, int B2, float alpha)
{
    constexpr int BK = 32;
    constexpr int WM = BM / WRR;
    constexpr int WN = BN / WCC;
    constexpr int IT = WM / 16;
    constexpr int JT = WN / 8;
    static_assert(WRR * WCC == 8, "8 warps");

    // constant trip counts for cooperative loads (256 threads, float4 each)
    constexpr int A_TRIPS  = (BM * 8) / 256;            // A: BM x BK/4 float4
    constexpr int BT_TRIPS = (BN * 8) / 256;            // B NT: BN x BK/4 float4
    constexpr int BN_TRIPS = (BK * (BN / 4)) / 256;     // B NN: BK x BN/4 float4
    static_assert(A_TRIPS >= 1 && (BM * 8) % 256 == 0, "A tile divisible");
    static_assert((BN * 8) % 256 == 0, "B NT tile divisible");
    static_assert((BK * (BN / 4)) % 256 == 0, "B NN tile divisible");

    int z = blockIdx.z;
    int i1 = z / B2, i2 = z - i1 * B2;
    const float* A  = A0 + (size_t)i1 * sA1 + (size_t)i2 * sA2;
    const float* Bp = B0 + (size_t)i1 * sB1 + (size_t)i2 * sB2;
    float*       Cp = C0 + (size_t)i1 * sC1 + (size_t)i2 * sC2;

    __shared__ unsigned As[BM][BK + 4];
    constexpr int BSR = TRB ? BN : BK;
    constexpr int BSC = TRB ? (BK + 4) : (BN + 8);
    __shared__ unsigned Bs[BSR][BSC];

    const int tid  = threadIdx.x;
    const int lane = tid & 31;
    const int wid  = tid >> 5;
    const int wr   = wid / WCC;
    const int wc   = wid % WCC;
    const int g    = lane >> 2;   // groupID 0..7
    const int tq   = lane & 3;    // threadID_in_group 0..3

    const int rowBase = blockIdx.y * BM;
    const int colBase = blockIdx.x * BN;

    float c[IT][JT][4];
    #pragma unroll
    for (int i = 0; i < IT; i++)
        #pragma unroll
        for (int j = 0; j < JT; j++)
            c[i][j][0] = c[i][j][1] = c[i][j][2] = c[i][j][3] = 0.f;

    for (int k0 = 0; k0 < K; k0 += BK) {
        // ---- A tile: BM x BK (K-contiguous), convert to tf32
        #pragma unroll
        for (int it = 0; it < A_TRIPS; it++) {
            int t = tid + it * 256;
            int r = t >> 3, c4 = (t & 7) << 2;
            float4 v = *reinterpret_cast<const float4*>(
                A + (size_t)(rowBase + r) * K + k0 + c4);
            As[r][c4 + 0] = f2tf(v.x); As[r][c4 + 1] = f2tf(v.y);
            As[r][c4 + 2] = f2tf(v.z); As[r][c4 + 3] = f2tf(v.w);
        }
        // ---- B tile
        if (TRB) {
            #pragma unroll
            for (int it = 0; it < BT_TRIPS; it++) {
                int t = tid + it * 256;
                int r = t >> 3, c4 = (t & 7) << 2;
                float4 v = *reinterpret_cast<const float4*>(
                    Bp + (size_t)(colBase + r) * K + k0 + c4);
                Bs[r][c4 + 0] = f2tf(v.x); Bs[r][c4 + 1] = f2tf(v.y);
                Bs[r][c4 + 2] = f2tf(v.z); Bs[r][c4 + 3] = f2tf(v.w);
            }
        } else {
            #pragma unroll
            for (int it = 0; it < BN_TRIPS; it++) {
                int t = tid + it * 256;
                int r = t / (BN / 4), c4 = (t % (BN / 4)) << 2;
                float4 v = *reinterpret_cast<const float4*>(
                    Bp + (size_t)(k0 + r) * N + colBase + c4);
                Bs[r][c4 + 0] = f2tf(v.x); Bs[r][c4 + 1] = f2tf(v.y);
                Bs[r][c4 + 2] = f2tf(v.z); Bs[r][c4 + 3] = f2tf(v.w);
            }
        }
        __syncthreads();

        #pragma unroll
        for (int ks = 0; ks < BK; ks += 8) {
            unsigned a[IT][4], b[JT][2];
            #pragma unroll
            for (int i = 0; i < IT; i++) {
                int m = wr * WM + i * 16;
                a[i][0] = As[m + g][ks + tq];
                a[i][1] = As[m + g + 8][ks + tq];
                a[i][2] = As[m + g][ks + tq + 4];
                a[i][3] = As[m + g + 8][ks + tq + 4];
            }
            #pragma unroll
            for (int j = 0; j < JT; j++) {
                int n = wc * WN + j * 8;
                if (TRB) {
                    b[j][0] = Bs[n + g][ks + tq];
                    b[j][1] = Bs[n + g][ks + tq + 4];
                } else {
                    b[j][0] = Bs[ks + tq][n + g];
                    b[j][1] = Bs[ks + tq + 4][n + g];
                }
            }
            #pragma unroll
            for (int i = 0; i < IT; i++)
                #pragma unroll
                for (int j = 0; j < JT; j++)
                    asm volatile(
                        "mma.sync.aligned.m16n8k8.row.col.f32.tf32.tf32.f32 "
                        "{%0,%1,%2,%3}, {%4,%5,%6,%7}, {%8,%9}, {%0,%1,%2,%3};\n"
                        : "+f"(c[i][j][0]), "+f"(c[i][j][1]),
                          "+f"(c[i][j][2]), "+f"(c[i][j][3])
                        : "r"(a[i][0]), "r"(a[i][1]), "r"(a[i][2]), "r"(a[i][3]),
                          "r"(b[j][0]), "r"(b[j][1]));
        }
        __syncthreads();
    }

    #pragma unroll
    for (int i = 0; i < IT; i++) {
        int row = rowBase + wr * WM + i * 16 + g;
        float bv0 = BIAS ? bias[row] : 0.f;
        float bv1 = BIAS ? bias[row + 8] : 0.f;
        #pragma unroll
        for (int j = 0; j < JT; j++) {
            int col = colBase + wc * WN + j * 8 + 2 * tq;
            Cp[(size_t)row * N + col]           = alpha * c[i][j][0] + bv0;
            Cp[(size_t)row * N + col + 1]       = alpha * c[i][j][1] + bv0;
            Cp[(size_t)(row + 8) * N + col]     = alpha * c[i][j][2] + bv1;
            Cp[(size_t)(row + 8) * N + col + 1] = alpha * c[i][j][3] + bv1;
        }
    }
}

// ---------------------------------------------------------------------------
// fp32 SGEMM for the tiny GEMMs (dots, attn@Wv). 64x64 tiles, 256 threads.
// ---------------------------------------------------------------------------
template <int BM, int BN, int BK, int TM, int TN, bool TRB, bool BIAS>
__global__ void __launch_bounds__((BM / TM) * (BN / TN))
sgemm(const float* __restrict__ A0, const float* __restrict__ B0,
      float* __restrict__ C0, const float* __restrict__ bias,
      int M, int N, int K,
      long long sA1, long long sA2, long long sB1, long long sB2,
      long long sC1, long long sC2, int B2, float alpha)
{
    constexpr int THREADS = (BM / TM) * (BN / TN);
    constexpr int A_TRIPS = (BM * BK / 4) / THREADS;
    constexpr int B_TRIPS = (BN * BK / 4) / THREADS;
    static_assert((BM * BK / 4) % THREADS == 0, "A tile divisible");
    static_assert((BN * BK / 4) % THREADS == 0, "B tile divisible");

    int z = blockIdx.z;
    int i1 = z / B2;
    int i2 = z - i1 * B2;
    const float* A  = A0 + (size_t)i1 * sA1 + (size_t)i2 * sA2;
    const float* Bp = B0 + (size_t)i1 * sB1 + (size_t)i2 * sB2;
    float*       Cp = C0 + (size_t)i1 * sC1 + (size_t)i2 * sC2;

    __shared__ float As[BK][BM + 4];
    __shared__ float Bs[BK][BN + 4];

    const int tid = threadIdx.x;
    const int tn  = tid % (BN / TN);
    const int tm  = tid / (BN / TN);
    const int rowC = blockIdx.y * BM + tm * TM;
    const int colC = blockIdx.x * BN + tn * TN;

    float acc[TM][TN] = {};

    for (int k0 = 0; k0 < K; k0 += BK) {
        #pragma unroll
        for (int it = 0; it < A_TRIPS; it++) {
            int t  = tid + it * THREADS;
            int r  = t / (BK / 4);
            int c4 = (t % (BK / 4)) * 4;
            float4 v = *reinterpret_cast<const float4*>(
                A + (size_t)(blockIdx.y * BM + r) * K + k0 + c4);
            As[c4 + 0][r] = v.x; As[c4 + 1][r] = v.y;
            As[c4 + 2][r] = v.z; As[c4 + 3][r] = v.w;
        }
        if (TRB) {
            #pragma unroll
            for (int it = 0; it < B_TRIPS; it++) {
                int t  = tid + it * THREADS;
                int r  = t / (BK / 4);
                int c4 = (t % (BK / 4)) * 4;
                float4 v = *reinterpret_cast<const float4*>(
                    Bp + (size_t)(blockIdx.x * BN + r) * K + k0 + c4);
                Bs[c4 + 0][r] = v.x; Bs[c4 + 1][r] = v.y;
                Bs[c4 + 2][r] = v.z; Bs[c4 + 3][r] = v.w;
            }
        } else {
            #pragma unroll
            for (int it = 0; it < B_TRIPS; it++) {
                int t  = tid + it * THREADS;
                int r  = t / (BN / 4);
                int c4 = (t % (BN / 4)) * 4;
                float4 v = *reinterpret_cast<const float4*>(
                    Bp + (size_t)(k0 + r) * N + blockIdx.x * BN + c4);
                *reinterpret_cast<float4*>(&Bs[r][c4]) = v;
            }
        }
        __syncthreads();

        #pragma unroll
        for (int k = 0; k < BK; k++) {
            float ra[TM], rb[TN];
            #pragma unroll
            for (int i = 0; i < TM; i++) ra[i] = As[k][tm * TM + i];
            #pragma unroll
            for (int j = 0; j < TN; j++) rb[j] = Bs[k][tn * TN + j];
            #pragma unroll
            for (int i = 0; i < TM; i++)
                #pragma unroll
                for (int j = 0; j < TN; j++)
                    acc[i][j] = fmaf(ra[i], rb[j], acc[i][j]);
        }
        __syncthreads();
    }

    #pragma unroll
    for (int i = 0; i < TM; i++) {
        float bv = BIAS ? bias[rowC + i] : 0.0f;
        #pragma unroll
        for (int j = 0; j < TN; j++)
            Cp[(size_t)(rowC + i) * N + colC + j] = alpha * acc[i][j] + bv;
    }
}

// ---------------------------------------------------------------------------
// Softmax over rows of 64 (one warp per row), in place.
// ---------------------------------------------------------------------------
__global__ void softmax64(float* __restrict__ dots)
{
    int warp = (blockIdx.x * blockDim.x + threadIdx.x) >> 5;
    int lane = threadIdx.x & 31;
    float* row = dots + (size_t)warp * 64;

    float a = row[lane];
    float b = row[lane + 32];
    float m = fmaxf(a, b);
    #pragma unroll
    for (int o = 16; o > 0; o >>= 1) m = fmaxf(m, __shfl_xor_sync(0xffffffffu, m, o));
    float e1 = __expf(a - m);
    float e2 = __expf(b - m);
    float s = e1 + e2;
    #pragma unroll
    for (int o = 16; o > 0; o >>= 1) s += __shfl_xor_sync(0xffffffffu, s, o);
    float inv = 1.0f / s;
    row[lane]      = e1 * inv;
    row[lane + 32] = e2 * inv;
}

extern "C" void kernel_launch(void* const* d_in, const int* in_sizes, int n_in,
                              void* d_out, int out_size)
{
    const float* f_m  = (const float*)d_in[0];
    const float* f_n  = (const float*)d_in[1];
    const float* Wq   = (const float*)d_in[2];
    const float* Wkv  = (const float*)d_in[3];
    const float* Wout = (const float*)d_in[4];
    const float* bout = (const float*)d_in[5];
    float* out = (float*)d_out;

    float *G, *T, *dots, *U, *Mm;
    cudaGetSymbolAddress((void**)&G,    g_G);
    cudaGetSymbolAddress((void**)&T,    g_T);
    cudaGetSymbolAddress((void**)&dots, g_dots);
    cudaGetSymbolAddress((void**)&U,    g_U);
    cudaGetSymbolAddress((void**)&Mm,   g_M);

    const long long CF  = (long long)CDIM * NSP;
    const long long CC  = (long long)CDIM * CDIM;
    const long long THD = (long long)CDIM * DH;

    // 1) G[b] = f_m[b] @ f_n[b]^T   (M=512, N=512, K=4096, NT)  [tf32]
    tf32gemm<128, 128, 2, 4, true, false><<<dim3(4, 4, BATCH), 256>>>(
        f_m, f_n, G, nullptr, CDIM, CDIM, NSP,
        CF, 0, CF, 0, CC, 0, 1, 1.0f);

    // 2) T[b,h] = G[b] @ Wk_h^T    (M=512, N=64, K=512, NT)  [tf32]
    tf32gemm<64, 64, 2, 4, true, false><<<dim3(1, 8, BATCH * NHEADS), 256>>>(
        G, Wkv, T, nullptr, CDIM, DH, CDIM,
        CC, 0, 0, (long long)DH * CDIM, (long long)NHEADS * THD, THD,
        NHEADS, 1.0f);

    // 3) dots[b,h] = (Wq_h @ T[b,h]) * scale   (M=64, N=64, K=512, NN) [fp32]
    sgemm<64, 64, 16, 4, 4, false, false><<<dim3(1, 1, BATCH * NHEADS), 256>>>(
        Wq, T, dots, nullptr, DH, DH, CDIM,
        0, (long long)DH * CDIM, (long long)NHEADS * THD, THD,
        (long long)NHEADS * DH * DH, (long long)DH * DH,
        NHEADS, 0.125f);

    // 4) attn = softmax(dots)
    softmax64<<<BATCH * NHEADS * DH / 8, 256>>>(dots);

    // 5) U[b] rows (h*64+i) = attn[b,h] @ Wv_h  (M=64, N=512, K=64, NN) [fp32]
    sgemm<64, 64, 16, 4, 4, false, false><<<dim3(8, 1, BATCH * NHEADS), 256>>>(
        dots, Wkv + (size_t)CDIM * CDIM, U, nullptr, DH, CDIM, DH,
        (long long)NHEADS * DH * DH, (long long)DH * DH,
        0, (long long)DH * CDIM,
        CC, (long long)DH * CDIM,
        NHEADS, 1.0f);

    // 6) M[b] = Wout @ U[b]   (M=512, N=512, K=512, NN)  [tf32]
    tf32gemm<128, 128, 2, 4, false, false><<<dim3(4, 4, BATCH), 256>>>(
        Wout, U, Mm, nullptr, CDIM, CDIM, CDIM,
        0, 0, CC, 0, CC, 0, 1, 1.0f);

    // 7) out[b] = M[b] @ f_n[b] + bout   (M=512, N=4096, K=512, NN, bias) [tf32]
    tf32gemm<128, 128, 2, 4, false, true><<<dim3(32, 4, BATCH), 256>>>(
        Mm, f_n, out, bout, CDIM, NSP, CDIM,
        CC, 0, CF, 0, CF, 0, 1, 1.0f);
}

// round 6
// speedup vs baseline: 2.3718x; 1.2612x over previous
#include <cuda_runtime.h>

// CrossAttention_5385888989393 — reduced channel-attention, TF32 tensor cores,
// double-buffered pipelined mainloop (BK=16, 2 smem stages, reg prefetch).
//
//   G[b]    = f_m[b] @ f_n[b]^T          (NT, K=4096)  [tf32]
//   T[b,h]  = G[b] @ Wk_h^T              (NT, K=512)   [tf32]
//   dots    = (Wq_h @ T[b,h]) * scale    (NN, K=512)   [fp32]
//   attn    = softmax(dots)
//   U[b]    = attn[b,h] @ Wv_h           (NN, K=64)    [fp32]
//   M[b]    = Wout @ U[b]                (NN, K=512)   [tf32]
//   out[b]  = M[b] @ f_n[b] + bout       (NN, K=512)   [tf32]

#define BATCH 8
#define NHEADS 8
#define DH 64
#define CDIM 512
#define NSP 4096

__device__ float g_G[BATCH * CDIM * CDIM];
__device__ float g_T[BATCH * NHEADS * CDIM * DH];
__device__ float g_dots[BATCH * NHEADS * DH * DH];
__device__ float g_U[BATCH * CDIM * CDIM];
__device__ float g_M[BATCH * CDIM * CDIM];

__device__ __forceinline__ unsigned f2tf(float f) {
    unsigned u;
    asm("cvt.rna.tf32.f32 %0, %1;" : "=r"(u) : "f"(f));
    return u;
}

// ---------------------------------------------------------------------------
// Pipelined TF32 GEMM via mma.sync.aligned.m16n8k8.row.col.f32.tf32.tf32.f32
//   C[M,N] = alpha * A(M,K) * op(B) (+ bias[m]);  A row-major.
//   TRB=true : B is (N,K) row-major  [NT];  TRB=false: B is (K,N) [NN]
//   256 threads = 8 warps (WRR x WCC); BK=16; 2-stage smem double buffer.
// ---------------------------------------------------------------------------
template <int BM, int BN, int WRR, int WCC, bool TRB, bool BIAS>
__global__ void __launch_bounds__(256)
tf32gemm(const float* __restrict__ A0, const float* __restrict__ B0,
         float* __restrict__ C0, const float* __restrict__ bias,
         int M, int N, int K,
         long long sA1, long long sA2, long long sB1, long long sB2,
         long long sC1, long long sC2, int B2, float alpha)
{
    constexpr int BK = 16;
    constexpr int WM = BM / WRR;
    constexpr int WN = BN / WCC;
    constexpr int IT = WM / 16;
    constexpr int JT = WN / 8;
    static_assert(WRR * WCC == 8, "8 warps");

    constexpr int A_TRIPS   = (BM * (BK / 4)) / 256;       // float4 per thread
    constexpr int BT_TRIPS  = (BN * (BK / 4)) / 256;       // NT
    constexpr int BNN_TRIPS = (BK * (BN / 4)) / 256;       // NN
    constexpr int B_TRIPS   = TRB ? BT_TRIPS : BNN_TRIPS;
    static_assert((BM * (BK / 4)) % 256 == 0, "A tile divisible");
    static_assert((BN * (BK / 4)) % 256 == 0, "B NT tile divisible");
    static_assert((BK * (BN / 4)) % 256 == 0, "B NN tile divisible");

    __shared__ unsigned As[2][BM][BK + 4];
    constexpr int BSR = TRB ? BN : BK;
    constexpr int BSC = TRB ? (BK + 4) : (BN + 8);
    __shared__ unsigned Bs[2][BSR][BSC];

    int z = blockIdx.z;
    int i1 = z / B2, i2 = z - i1 * B2;
    const float* A  = A0 + (size_t)i1 * sA1 + (size_t)i2 * sA2;
    const float* Bp = B0 + (size_t)i1 * sB1 + (size_t)i2 * sB2;
    float*       Cp = C0 + (size_t)i1 * sC1 + (size_t)i2 * sC2;

    const int tid  = threadIdx.x;
    const int lane = tid & 31;
    const int wid  = tid >> 5;
    const int wr   = wid / WCC;
    const int wc   = wid % WCC;
    const int g    = lane >> 2;   // groupID 0..7
    const int tq   = lane & 3;    // threadID_in_group 0..3

    const int rowBase = blockIdx.y * BM;
    const int colBase = blockIdx.x * BN;

    float c[IT][JT][4];
    #pragma unroll
    for (int i = 0; i < IT; i++)
        #pragma unroll
        for (int j = 0; j < JT; j++)
            c[i][j][0] = c[i][j][1] = c[i][j][2] = c[i][j][3] = 0.f;

    float4 pa[A_TRIPS], pb[B_TRIPS];

    // ---- prologue: fetch tile 0 into registers
    #pragma unroll
    for (int it = 0; it < A_TRIPS; it++) {
        int t = tid + it * 256;
        pa[it] = *reinterpret_cast<const float4*>(
            A + (size_t)(rowBase + (t >> 2)) * K + ((t & 3) << 2));
    }
    if (TRB) {
        #pragma unroll
        for (int it = 0; it < B_TRIPS; it++) {
            int t = tid + it * 256;
            pb[it] = *reinterpret_cast<const float4*>(
                Bp + (size_t)(colBase + (t >> 2)) * K + ((t & 3) << 2));
        }
    } else {
        #pragma unroll
        for (int it = 0; it < B_TRIPS; it++) {
            int t = tid + it * 256;
            pb[it] = *reinterpret_cast<const float4*>(
                Bp + (size_t)(t / (BN / 4)) * N + colBase + ((t % (BN / 4)) << 2));
        }
    }
    // store tile 0 to stage 0
    #pragma unroll
    for (int it = 0; it < A_TRIPS; it++) {
        int t = tid + it * 256;
        int r = t >> 2, c4 = (t & 3) << 2;
        As[0][r][c4 + 0] = f2tf(pa[it].x); As[0][r][c4 + 1] = f2tf(pa[it].y);
        As[0][r][c4 + 2] = f2tf(pa[it].z); As[0][r][c4 + 3] = f2tf(pa[it].w);
    }
    #pragma unroll
    for (int it = 0; it < B_TRIPS; it++) {
        int t = tid + it * 256;
        int r  = TRB ? (t >> 2) : (t / (BN / 4));
        int c4 = TRB ? ((t & 3) << 2) : ((t % (BN / 4)) << 2);
        Bs[0][r][c4 + 0] = f2tf(pb[it].x); Bs[0][r][c4 + 1] = f2tf(pb[it].y);
        Bs[0][r][c4 + 2] = f2tf(pb[it].z); Bs[0][r][c4 + 3] = f2tf(pb[it].w);
    }
    __syncthreads();

    int buf = 0;
    for (int k0 = 0; k0 < K; k0 += BK) {
        const bool has_next = (k0 + BK) < K;
        // ---- prefetch next tile into registers (latency hidden by compute)
        if (has_next) {
            const int kn = k0 + BK;
            #pragma unroll
            for (int it = 0; it < A_TRIPS; it++) {
                int t = tid + it * 256;
                pa[it] = *reinterpret_cast<const float4*>(
                    A + (size_t)(rowBase + (t >> 2)) * K + kn + ((t & 3) << 2));
            }
            if (TRB) {
                #pragma unroll
                for (int it = 0; it < B_TRIPS; it++) {
                    int t = tid + it * 256;
                    pb[it] = *reinterpret_cast<const float4*>(
                        Bp + (size_t)(colBase + (t >> 2)) * K + kn + ((t & 3) << 2));
                }
            } else {
                #pragma unroll
                for (int it = 0; it < B_TRIPS; it++) {
                    int t = tid + it * 256;
                    pb[it] = *reinterpret_cast<const float4*>(
                        Bp + (size_t)(kn + t / (BN / 4)) * N + colBase + ((t % (BN / 4)) << 2));
                }
            }
        }

        // ---- compute current stage
        #pragma unroll
        for (int ks = 0; ks < BK; ks += 8) {
            unsigned a[IT][4], b[JT][2];
            #pragma unroll
            for (int i = 0; i < IT; i++) {
                int m = wr * WM + i * 16;
                a[i][0] = As[buf][m + g][ks + tq];
                a[i][1] = As[buf][m + g + 8][ks + tq];
                a[i][2] = As[buf][m + g][ks + tq + 4];
                a[i][3] = As[buf][m + g + 8][ks + tq + 4];
            }
            #pragma unroll
            for (int j = 0; j < JT; j++) {
                int n = wc * WN + j * 8;
                if (TRB) {
                    b[j][0] = Bs[buf][n + g][ks + tq];
                    b[j][1] = Bs[buf][n + g][ks + tq + 4];
                } else {
                    b[j][0] = Bs[buf][ks + tq][n + g];
                    b[j][1] = Bs[buf][ks + tq + 4][n + g];
                }
            }
            #pragma unroll
            for (int i = 0; i < IT; i++)
                #pragma unroll
                for (int j = 0; j < JT; j++)
                    asm volatile(
                        "mma.sync.aligned.m16n8k8.row.col.f32.tf32.tf32.f32 "
                        "{%0,%1,%2,%3}, {%4,%5,%6,%7}, {%8,%9}, {%0,%1,%2,%3};\n"
                        : "+f"(c[i][j][0]), "+f"(c[i][j][1]),
                          "+f"(c[i][j][2]), "+f"(c[i][j][3])
                        : "r"(a[i][0]), "r"(a[i][1]), "r"(a[i][2]), "r"(a[i][3]),
                          "r"(b[j][0]), "r"(b[j][1]));
        }

        // ---- store next tile into the other stage, one barrier per tile
        if (has_next) {
            int nb = buf ^ 1;
            #pragma unroll
            for (int it = 0; it < A_TRIPS; it++) {
                int t = tid + it * 256;
                int r = t >> 2, c4 = (t & 3) << 2;
                As[nb][r][c4 + 0] = f2tf(pa[it].x); As[nb][r][c4 + 1] = f2tf(pa[it].y);
                As[nb][r][c4 + 2] = f2tf(pa[it].z); As[nb][r][c4 + 3] = f2tf(pa[it].w);
            }
            #pragma unroll
            for (int it = 0; it < B_TRIPS; it++) {
                int t = tid + it * 256;
                int r  = TRB ? (t >> 2) : (t / (BN / 4));
                int c4 = TRB ? ((t & 3) << 2) : ((t % (BN / 4)) << 2);
                Bs[nb][r][c4 + 0] = f2tf(pb[it].x); Bs[nb][r][c4 + 1] = f2tf(pb[it].y);
                Bs[nb][r][c4 + 2] = f2tf(pb[it].z); Bs[nb][r][c4 + 3] = f2tf(pb[it].w);
            }
            __syncthreads();
            buf = nb;
        }
    }

    // ---- epilogue
    #pragma unroll
    for (int i = 0; i < IT; i++) {
        int row = rowBase + wr * WM + i * 16 + g;
        float bv0 = BIAS ? bias[row] : 0.f;
        float bv1 = BIAS ? bias[row + 8] : 0.f;
        #pragma unroll
        for (int j = 0; j < JT; j++) {
            int col = colBase + wc * WN + j * 8 + 2 * tq;
            Cp[(size_t)row * N + col]           = alpha * c[i][j][0] + bv0;
            Cp[(size_t)row * N + col + 1]       = alpha * c[i][j][1] + bv0;
            Cp[(size_t)(row + 8) * N + col]     = alpha * c[i][j][2] + bv1;
            Cp[(size_t)(row + 8) * N + col + 1] = alpha * c[i][j][3] + bv1;
        }
    }
}

// ---------------------------------------------------------------------------
// fp32 SGEMM for the tiny GEMMs (dots, attn@Wv). 64x64 tiles, 256 threads.
// ---------------------------------------------------------------------------
template <int BM, int BN, int BK, int TM, int TN, bool TRB, bool BIAS>
__global__ void __launch_bounds__((BM / TM) * (BN / TN))
sgemm(const float* __restrict__ A0, const float* __restrict__ B0,
      float* __restrict__ C0, const float* __restrict__ bias,
      int M, int N, int K,
      long long sA1, long long sA2, long long sB1, long long sB2,
      long long sC1, long long sC2, int B2, float alpha)
{
    constexpr int THREADS = (BM / TM) * (BN / TN);
    constexpr int A_TRIPS = (BM * BK / 4) / THREADS;
    constexpr int B_TRIPS = (BN * BK / 4) / THREADS;
    static_assert((BM * BK / 4) % THREADS == 0, "A tile divisible");
    static_assert((BN * BK / 4) % THREADS == 0, "B tile divisible");

    int z = blockIdx.z;
    int i1 = z / B2;
    int i2 = z - i1 * B2;
    const float* A  = A0 + (size_t)i1 * sA1 + (size_t)i2 * sA2;
    const float* Bp = B0 + (size_t)i1 * sB1 + (size_t)i2 * sB2;
    float*       Cp = C0 + (size_t)i1 * sC1 + (size_t)i2 * sC2;

    __shared__ float As[BK][BM + 4];
    __shared__ float Bs[BK][BN + 4];

    const int tid = threadIdx.x;
    const int tn  = tid % (BN / TN);
    const int tm  = tid / (BN / TN);
    const int rowC = blockIdx.y * BM + tm * TM;
    const int colC = blockIdx.x * BN + tn * TN;

    float acc[TM][TN] = {};

    for (int k0 = 0; k0 < K; k0 += BK) {
        #pragma unroll
        for (int it = 0; it < A_TRIPS; it++) {
            int t  = tid + it * THREADS;
            int r  = t / (BK / 4);
            int c4 = (t % (BK / 4)) * 4;
            float4 v = *reinterpret_cast<const float4*>(
                A + (size_t)(blockIdx.y * BM + r) * K + k0 + c4);
            As[c4 + 0][r] = v.x; As[c4 + 1][r] = v.y;
            As[c4 + 2][r] = v.z; As[c4 + 3][r] = v.w;
        }
        if (TRB) {
            #pragma unroll
            for (int it = 0; it < B_TRIPS; it++) {
                int t  = tid + it * THREADS;
                int r  = t / (BK / 4);
                int c4 = (t % (BK / 4)) * 4;
                float4 v = *reinterpret_cast<const float4*>(
                    Bp + (size_t)(blockIdx.x * BN + r) * K + k0 + c4);
                Bs[c4 + 0][r] = v.x; Bs[c4 + 1][r] = v.y;
                Bs[c4 + 2][r] = v.z; Bs[c4 + 3][r] = v.w;
            }
        } else {
            #pragma unroll
            for (int it = 0; it < B_TRIPS; it++) {
                int t  = tid + it * THREADS;
                int r  = t / (BN / 4);
                int c4 = (t % (BN / 4)) * 4;
                float4 v = *reinterpret_cast<const float4*>(
                    Bp + (size_t)(k0 + r) * N + blockIdx.x * BN + c4);
                *reinterpret_cast<float4*>(&Bs[r][c4]) = v;
            }
        }
        __syncthreads();

        #pragma unroll
        for (int k = 0; k < BK; k++) {
            float ra[TM], rb[TN];
            #pragma unroll
            for (int i = 0; i < TM; i++) ra[i] = As[k][tm * TM + i];
            #pragma unroll
            for (int j = 0; j < TN; j++) rb[j] = Bs[k][tn * TN + j];
            #pragma unroll
            for (int i = 0; i < TM; i++)
                #pragma unroll
                for (int j = 0; j < TN; j++)
                    acc[i][j] = fmaf(ra[i], rb[j], acc[i][j]);
        }
        __syncthreads();
    }

    #pragma unroll
    for (int i = 0; i < TM; i++) {
        float bv = BIAS ? bias[rowC + i] : 0.0f;
        #pragma unroll
        for (int j = 0; j < TN; j++)
            Cp[(size_t)(rowC + i) * N + colC + j] = alpha * acc[i][j] + bv;
    }
}

// ---------------------------------------------------------------------------
// Softmax over rows of 64 (one warp per row), in place.
// ---------------------------------------------------------------------------
__global__ void softmax64(float* __restrict__ dots)
{
    int warp = (blockIdx.x * blockDim.x + threadIdx.x) >> 5;
    int lane = threadIdx.x & 31;
    float* row = dots + (size_t)warp * 64;

    float a = row[lane];
    float b = row[lane + 32];
    float m = fmaxf(a, b);
    #pragma unroll
    for (int o = 16; o > 0; o >>= 1) m = fmaxf(m, __shfl_xor_sync(0xffffffffu, m, o));
    float e1 = __expf(a - m);
    float e2 = __expf(b - m);
    float s = e1 + e2;
    #pragma unroll
    for (int o = 16; o > 0; o >>= 1) s += __shfl_xor_sync(0xffffffffu, s, o);
    float inv = 1.0f / s;
    row[lane]      = e1 * inv;
    row[lane + 32] = e2 * inv;
}

extern "C" void kernel_launch(void* const* d_in, const int* in_sizes, int n_in,
                              void* d_out, int out_size)
{
    const float* f_m  = (const float*)d_in[0];
    const float* f_n  = (const float*)d_in[1];
    const float* Wq   = (const float*)d_in[2];
    const float* Wkv  = (const float*)d_in[3];
    const float* Wout = (const float*)d_in[4];
    const float* bout = (const float*)d_in[5];
    float* out = (float*)d_out;

    float *G, *T, *dots, *U, *Mm;
    cudaGetSymbolAddress((void**)&G,    g_G);
    cudaGetSymbolAddress((void**)&T,    g_T);
    cudaGetSymbolAddress((void**)&dots, g_dots);
    cudaGetSymbolAddress((void**)&U,    g_U);
    cudaGetSymbolAddress((void**)&Mm,   g_M);

    const long long CF  = (long long)CDIM * NSP;
    const long long CC  = (long long)CDIM * CDIM;
    const long long THD = (long long)CDIM * DH;

    // 1) G[b] = f_m[b] @ f_n[b]^T   (M=512, N=512, K=4096, NT)  [tf32]
    tf32gemm<128, 128, 2, 4, true, false><<<dim3(4, 4, BATCH), 256>>>(
        f_m, f_n, G, nullptr, CDIM, CDIM, NSP,
        CF, 0, CF, 0, CC, 0, 1, 1.0f);

    // 2) T[b,h] = G[b] @ Wk_h^T    (M=512, N=64, K=512, NT)  [tf32]
    tf32gemm<64, 64, 2, 4, true, false><<<dim3(1, 8, BATCH * NHEADS), 256>>>(
        G, Wkv, T, nullptr, CDIM, DH, CDIM,
        CC, 0, 0, (long long)DH * CDIM, (long long)NHEADS * THD, THD,
        NHEADS, 1.0f);

    // 3) dots[b,h] = (Wq_h @ T[b,h]) * scale   (M=64, N=64, K=512, NN) [fp32]
    sgemm<64, 64, 16, 4, 4, false, false><<<dim3(1, 1, BATCH * NHEADS), 256>>>(
        Wq, T, dots, nullptr, DH, DH, CDIM,
        0, (long long)DH * CDIM, (long long)NHEADS * THD, THD,
        (long long)NHEADS * DH * DH, (long long)DH * DH,
        NHEADS, 0.125f);

    // 4) attn = softmax(dots)
    softmax64<<<BATCH * NHEADS * DH / 8, 256>>>(dots);

    // 5) U[b] rows (h*64+i) = attn[b,h] @ Wv_h  (M=64, N=512, K=64, NN) [fp32]
    sgemm<64, 64, 16, 4, 4, false, false><<<dim3(8, 1, BATCH * NHEADS), 256>>>(
        dots, Wkv + (size_t)CDIM * CDIM, U, nullptr, DH, CDIM, DH,
        (long long)NHEADS * DH * DH, (long long)DH * DH,
        0, (long long)DH * CDIM,
        CC, (long long)DH * CDIM,
        NHEADS, 1.0f);

    // 6) M[b] = Wout @ U[b]   (M=512, N=512, K=512, NN)  [tf32]
    tf32gemm<128, 128, 2, 4, false, false><<<dim3(4, 4, BATCH), 256>>>(
        Wout, U, Mm, nullptr, CDIM, CDIM, CDIM,
        0, 0, CC, 0, CC, 0, 1, 1.0f);

    // 7) out[b] = M[b] @ f_n[b] + bout   (M=512, N=4096, K=512, NN, bias) [tf32]
    tf32gemm<128, 128, 2, 4, false, true><<<dim3(32, 4, BATCH), 256>>>(
        Mm, f_n, out, bout, CDIM, NSP, CDIM,
        CC, 0, CF, 0, CF, 0, 1, 1.0f);
}

// round 8
// speedup vs baseline: 2.8299x; 1.1932x over previous
#include <cuda_runtime.h>

// CrossAttention_5385888989393 — reduced channel-attention, TF32 tensor cores.
// R7: conversion hoisted out of GEMM mainloops (pre-convert inputs once,
// producer epilogues emit tf32), cp.async-fed BK=32 double-buffered mainloop.
//
//   cm = tf32(f_m); cn = tf32(f_n); cWk = tf32(Wkv[0:512]); cWout = tf32(Wout)
//   G[b]    = cm[b] @ cn[b]^T       (NT, K=4096)  [tf32, out tf32]
//   T[b,h]  = G[b] @ cWk_h^T        (NT, K=512)   [tf32, out fp32]
//   dots    = (Wq_h @ T[b,h])*scale (NN, K=512)   [fp32]
//   attn    = softmax(dots)
//   U[b]    = attn[b,h] @ Wv_h      (NN, K=64)    [fp32, out tf32]
//   M[b]    = cWout @ U[b]          (NN, K=512)   [tf32, out tf32]
//   out[b]  = M[b] @ cn[b] + bout   (NN, K=512)   [tf32, out fp32]

#define BATCH 8
#define NHEADS 8
#define DH 64
#define CDIM 512
#define NSP 4096

__device__ float g_G[BATCH * CDIM * CDIM];
__device__ float g_T[BATCH * NHEADS * CDIM * DH];
__device__ float g_dots[BATCH * NHEADS * DH * DH];
__device__ float g_U[BATCH * CDIM * CDIM];
__device__ float g_M[BATCH * CDIM * CDIM];
__device__ float g_cm[BATCH * CDIM * NSP];     // tf32(f_m)
__device__ float g_cn[BATCH * CDIM * NSP];     // tf32(f_n)
__device__ float g_cWk[CDIM * CDIM];           // tf32(Wkv k-half)
__device__ float g_cWout[CDIM * CDIM];         // tf32(Wout)

__device__ __forceinline__ unsigned f2tf(float f) {
    unsigned u;
    asm("cvt.rna.tf32.f32 %0, %1;" : "=r"(u) : "f"(f));
    return u;
}

__device__ __forceinline__ void cp16(void* sdst, const void* gsrc) {
    unsigned s = (unsigned)__cvta_generic_to_shared(sdst);
    asm volatile("cp.async.cg.shared.global [%0], [%1], 16;\n" :: "r"(s), "l"(gsrc));
}
__device__ __forceinline__ void cp_commit() {
    asm volatile("cp.async.commit_group;\n");
}

// ---------------------------------------------------------------------------
// Bulk tf32 conversion: out[i] = rna(in[i]), float4-wide.
// ---------------------------------------------------------------------------
__global__ void cvt_tf32_k(const float4* __restrict__ in, uint4* __restrict__ out, int n4)
{
    int i = blockIdx.x * blockDim.x + threadIdx.x;
    if (i < n4) {
        float4 v = in[i];
        uint4 o;
        o.x = f2tf(v.x); o.y = f2tf(v.y); o.z = f2tf(v.z); o.w = f2tf(v.w);
        out[i] = o;
    }
}

// ---------------------------------------------------------------------------
// cp.async-fed TF32 GEMM (operands already tf32-rounded in gmem).
//   C[M,N] = alpha * A(M,K) * op(B) (+ bias[m]); optionally tf32-round output.
//   BK=32, 2-stage smem double buffer, 256 threads = 8 warps (WRR x WCC).
// ---------------------------------------------------------------------------
template <int BM, int BN, int WRR, int WCC, bool TRB, bool BIAS, bool CVTOUT>
__global__ void __launch_bounds__(256)
tf32gemm_ca(const float* __restrict__ A0, const float* __restrict__ B0,
            float* __restrict__ C0, const float* __restrict__ bias,
            int M, int N, int K,
            long long sA1, long long sA2, long long sB1, long long sB2,
            long long sC1, long long sC2, int B2, float alpha)
{
    constexpr int BK = 32;
    constexpr int WM = BM / WRR;
    constexpr int WN = BN / WCC;
    constexpr int IT = WM / 16;
    constexpr int JT = WN / 8;
    static_assert(WRR * WCC == 8, "8 warps");

    constexpr int AW  = BK + 4;                       // 36 words/row, 144B (16B-mult)
    constexpr int BSR = TRB ? BN : BK;
    constexpr int BSC = TRB ? (BK + 4) : (BN + 8);    // NN rows: 544B (16B-mult)
    constexpr int A_WORDS = BM * AW;
    constexpr int B_WORDS = BSR * BSC;

    constexpr int A_T4   = (BM * (BK / 4)) / 256;     // float4 loads per thread
    constexpr int BT_T4  = (BN * (BK / 4)) / 256;
    constexpr int BNN_T4 = (BK * (BN / 4)) / 256;
    constexpr int B_T4   = TRB ? BT_T4 : BNN_T4;
    static_assert((BM * (BK / 4)) % 256 == 0, "A tile divisible");
    static_assert((BN * (BK / 4)) % 256 == 0, "B NT tile divisible");
    static_assert((BK * (BN / 4)) % 256 == 0, "B NN tile divisible");

    extern __shared__ unsigned sm[];
    unsigned* Asm = sm;                    // [2][BM][AW]
    unsigned* Bsm = sm + 2 * A_WORDS;      // [2][BSR][BSC]

    int z = blockIdx.z;
    int i1 = z / B2, i2 = z - i1 * B2;
    const float* A  = A0 + (size_t)i1 * sA1 + (size_t)i2 * sA2;
    const float* Bp = B0 + (size_t)i1 * sB1 + (size_t)i2 * sB2;
    float*       Cp = C0 + (size_t)i1 * sC1 + (size_t)i2 * sC2;

    const int tid  = threadIdx.x;
    const int lane = tid & 31;
    const int wid  = tid >> 5;
    const int wr   = wid / WCC;
    const int wc   = wid % WCC;
    const int g    = lane >> 2;
    const int tq   = lane & 3;

    const int rowBase = blockIdx.y * BM;
    const int colBase = blockIdx.x * BN;

    float c[IT][JT][4];
    #pragma unroll
    for (int i = 0; i < IT; i++)
        #pragma unroll
        for (int j = 0; j < JT; j++)
            c[i][j][0] = c[i][j][1] = c[i][j][2] = c[i][j][3] = 0.f;

    // ---- async tile loader for stage s at K offset k0
    auto load_tile = [&](int s, int k0) {
        #pragma unroll
        for (int it = 0; it < A_T4; it++) {
            int t = tid + it * 256;
            int r = t >> 3, c4 = (t & 7) << 2;          // BK/4 = 8 f4 per row
            cp16(&Asm[s * A_WORDS + r * AW + c4],
                 A + (size_t)(rowBase + r) * K + k0 + c4);
        }
        if (TRB) {
            #pragma unroll
            for (int it = 0; it < B_T4; it++) {
                int t = tid + it * 256;
                int r = t >> 3, c4 = (t & 7) << 2;
                cp16(&Bsm[s * B_WORDS + r * BSC + c4],
                     Bp + (size_t)(colBase + r) * K + k0 + c4);
            }
        } else {
            #pragma unroll
            for (int it = 0; it < B_T4; it++) {
                int t = tid + it * 256;
                int r = t / (BN / 4), c4 = (t % (BN / 4)) << 2;
                cp16(&Bsm[s * B_WORDS + r * BSC + c4],
                     Bp + (size_t)(k0 + r) * N + colBase + c4);
            }
        }
        cp_commit();
    };

    // prologue: stage 0 in flight
    load_tile(0, 0);

    int buf = 0;
    for (int k0 = 0; k0 < K; k0 += BK) {
        const bool has_next = (k0 + BK) < K;
        if (has_next) load_tile(buf ^ 1, k0 + BK);

        if (has_next) { asm volatile("cp.async.wait_group 1;\n"); }
        else          { asm volatile("cp.async.wait_group 0;\n"); }
        __syncthreads();   // stage `buf` visible to all threads

        const unsigned* Ab = Asm + buf * A_WORDS;
        const unsigned* Bb = Bsm + buf * B_WORDS;

        #pragma unroll
        for (int ks = 0; ks < BK; ks += 8) {
            unsigned a[IT][4], b[JT][2];
            #pragma unroll
            for (int i = 0; i < IT; i++) {
                int m = wr * WM + i * 16;
                a[i][0] = Ab[(m + g) * AW + ks + tq];
                a[i][1] = Ab[(m + g + 8) * AW + ks + tq];
                a[i][2] = Ab[(m + g) * AW + ks + tq + 4];
                a[i][3] = Ab[(m + g + 8) * AW + ks + tq + 4];
            }
            #pragma unroll
            for (int j = 0; j < JT; j++) {
                int n = wc * WN + j * 8;
                if (TRB) {
                    b[j][0] = Bb[(n + g) * BSC + ks + tq];
                    b[j][1] = Bb[(n + g) * BSC + ks + tq + 4];
                } else {
                    b[j][0] = Bb[(ks + tq) * BSC + n + g];
                    b[j][1] = Bb[(ks + tq + 4) * BSC + n + g];
                }
            }
            #pragma unroll
            for (int i = 0; i < IT; i++)
                #pragma unroll
                for (int j = 0; j < JT; j++)
                    asm volatile(
                        "mma.sync.aligned.m16n8k8.row.col.f32.tf32.tf32.f32 "
                        "{%0,%1,%2,%3}, {%4,%5,%6,%7}, {%8,%9}, {%0,%1,%2,%3};\n"
                        : "+f"(c[i][j][0]), "+f"(c[i][j][1]),
                          "+f"(c[i][j][2]), "+f"(c[i][j][3])
                        : "r"(a[i][0]), "r"(a[i][1]), "r"(a[i][2]), "r"(a[i][3]),
                          "r"(b[j][0]), "r"(b[j][1]));
        }
        __syncthreads();   // all reads of `buf` done before next load overwrites it
        buf ^= 1;
    }

    #pragma unroll
    for (int i = 0; i < IT; i++) {
        int row = rowBase + wr * WM + i * 16 + g;
        float bv0 = BIAS ? bias[row] : 0.f;
        float bv1 = BIAS ? bias[row + 8] : 0.f;
        #pragma unroll
        for (int j = 0; j < JT; j++) {
            int col = colBase + wc * WN + j * 8 + 2 * tq;
            float v00 = alpha * c[i][j][0] + bv0;
            float v01 = alpha * c[i][j][1] + bv0;
            float v10 = alpha * c[i][j][2] + bv1;
            float v11 = alpha * c[i][j][3] + bv1;
            if (CVTOUT) {
                v00 = __uint_as_float(f2tf(v00));
                v01 = __uint_as_float(f2tf(v01));
                v10 = __uint_as_float(f2tf(v10));
                v11 = __uint_as_float(f2tf(v11));
            }
            Cp[(size_t)row * N + col]           = v00;
            Cp[(size_t)row * N + col + 1]       = v01;
            Cp[(size_t)(row + 8) * N + col]     = v10;
            Cp[(size_t)(row + 8) * N + col + 1] = v11;
        }
    }
}

// ---------------------------------------------------------------------------
// fp32 SGEMM for the tiny GEMMs (dots, attn@Wv). Optional tf32-rounded output.
// ---------------------------------------------------------------------------
template <int BM, int BN, int BK, int TM, int TN, bool TRB, bool BIAS, bool CVTOUT>
__global__ void __launch_bounds__((BM / TM) * (BN / TN))
sgemm(const float* __restrict__ A0, const float* __restrict__ B0,
      float* __restrict__ C0, const float* __restrict__ bias,
      int M, int N, int K,
      long long sA1, long long sA2, long long sB1, long long sB2,
      long long sC1, long long sC2, int B2, float alpha)
{
    constexpr int THREADS = (BM / TM) * (BN / TN);
    constexpr int A_TRIPS = (BM * BK / 4) / THREADS;
    constexpr int B_TRIPS = (BN * BK / 4) / THREADS;
    static_assert((BM * BK / 4) % THREADS == 0, "A tile divisible");
    static_assert((BN * BK / 4) % THREADS == 0, "B tile divisible");

    int z = blockIdx.z;
    int i1 = z / B2;
    int i2 = z - i1 * B2;
    const float* A  = A0 + (size_t)i1 * sA1 + (size_t)i2 * sA2;
    const float* Bp = B0 + (size_t)i1 * sB1 + (size_t)i2 * sB2;
    float*       Cp = C0 + (size_t)i1 * sC1 + (size_t)i2 * sC2;

    __shared__ float As[BK][BM + 4];
    __shared__ float Bs[BK][BN + 4];

    const int tid = threadIdx.x;
    const int tn  = tid % (BN / TN);
    const int tm  = tid / (BN / TN);
    const int rowC = blockIdx.y * BM + tm * TM;
    const int colC = blockIdx.x * BN + tn * TN;

    float acc[TM][TN] = {};

    for (int k0 = 0; k0 < K; k0 += BK) {
        #pragma unroll
        for (int it = 0; it < A_TRIPS; it++) {
            int t  = tid + it * THREADS;
            int r  = t / (BK / 4);
            int c4 = (t % (BK / 4)) * 4;
            float4 v = *reinterpret_cast<const float4*>(
                A + (size_t)(blockIdx.y * BM + r) * K + k0 + c4);
            As[c4 + 0][r] = v.x; As[c4 + 1][r] = v.y;
            As[c4 + 2][r] = v.z; As[c4 + 3][r] = v.w;
        }
        if (TRB) {
            #pragma unroll
            for (int it = 0; it < B_TRIPS; it++) {
                int t  = tid + it * THREADS;
                int r  = t / (BK / 4);
                int c4 = (t % (BK / 4)) * 4;
                float4 v = *reinterpret_cast<const float4*>(
                    Bp + (size_t)(blockIdx.x * BN + r) * K + k0 + c4);
                Bs[c4 + 0][r] = v.x; Bs[c4 + 1][r] = v.y;
                Bs[c4 + 2][r] = v.z; Bs[c4 + 3][r] = v.w;
            }
        } else {
            #pragma unroll
            for (int it = 0; it < B_TRIPS; it++) {
                int t  = tid + it * THREADS;
                int r  = t / (BN / 4);
                int c4 = (t % (BN / 4)) * 4;
                float4 v = *reinterpret_cast<const float4*>(
                    Bp + (size_t)(k0 + r) * N + blockIdx.x * BN + c4);
                *reinterpret_cast<float4*>(&Bs[r][c4]) = v;
            }
        }
        __syncthreads();

        #pragma unroll
        for (int k = 0; k < BK; k++) {
            float ra[TM], rb[TN];
            #pragma unroll
            for (int i = 0; i < TM; i++) ra[i] = As[k][tm * TM + i];
            #pragma unroll
            for (int j = 0; j < TN; j++) rb[j] = Bs[k][tn * TN + j];
            #pragma unroll
            for (int i = 0; i < TM; i++)
                #pragma unroll
                for (int j = 0; j < TN; j++)
                    acc[i][j] = fmaf(ra[i], rb[j], acc[i][j]);
        }
        __syncthreads();
    }

    #pragma unroll
    for (int i = 0; i < TM; i++) {
        float bv = BIAS ? bias[rowC + i] : 0.0f;
        #pragma unroll
        for (int j = 0; j < TN; j++) {
            float v = alpha * acc[i][j] + bv;
            if (CVTOUT) v = __uint_as_float(f2tf(v));
            Cp[(size_t)(rowC + i) * N + colC + j] = v;
        }
    }
}

// ---------------------------------------------------------------------------
// Softmax over rows of 64 (one warp per row), in place.
// ---------------------------------------------------------------------------
__global__ void softmax64(float* __restrict__ dots)
{
    int warp = (blockIdx.x * blockDim.x + threadIdx.x) >> 5;
    int lane = threadIdx.x & 31;
    float* row = dots + (size_t)warp * 64;

    float a = row[lane];
    float b = row[lane + 32];
    float m = fmaxf(a, b);
    #pragma unroll
    for (int o = 16; o > 0; o >>= 1) m = fmaxf(m, __shfl_xor_sync(0xffffffffu, m, o));
    float e1 = __expf(a - m);
    float e2 = __expf(b - m);
    float s = e1 + e2;
    #pragma unroll
    for (int o = 16; o > 0; o >>= 1) s += __shfl_xor_sync(0xffffffffu, s, o);
    float inv = 1.0f / s;
    row[lane]      = e1 * inv;
    row[lane + 32] = e2 * inv;
}

extern "C" void kernel_launch(void* const* d_in, const int* in_sizes, int n_in,
                              void* d_out, int out_size)
{
    const float* f_m  = (const float*)d_in[0];
    const float* f_n  = (const float*)d_in[1];
    const float* Wq   = (const float*)d_in[2];
    const float* Wkv  = (const float*)d_in[3];
    const float* Wout = (const float*)d_in[4];
    const float* bout = (const float*)d_in[5];
    float* out = (float*)d_out;

    float *G, *T, *dots, *U, *Mm, *cm, *cn, *cWk, *cWout;
    cudaGetSymbolAddress((void**)&G,     g_G);
    cudaGetSymbolAddress((void**)&T,     g_T);
    cudaGetSymbolAddress((void**)&dots,  g_dots);
    cudaGetSymbolAddress((void**)&U,     g_U);
    cudaGetSymbolAddress((void**)&Mm,    g_M);
    cudaGetSymbolAddress((void**)&cm,    g_cm);
    cudaGetSymbolAddress((void**)&cn,    g_cn);
    cudaGetSymbolAddress((void**)&cWk,   g_cWk);
    cudaGetSymbolAddress((void**)&cWout, g_cWout);

    const long long CF  = (long long)CDIM * NSP;
    const long long CC  = (long long)CDIM * CDIM;
    const long long THD = (long long)CDIM * DH;

    // dynamic smem sizes (words: 2*BM*36 + 2*BSR*BSC, *4 bytes)
    constexpr int SM_128_NT = (2 * 128 * 36 + 2 * 128 * 36) * 4;   // 73728
    constexpr int SM_64_NT  = (2 * 64 * 36 + 2 * 64 * 36) * 4;     // 36864
    constexpr int SM_128_NN = (2 * 128 * 36 + 2 * 32 * 136) * 4;   // 71680

    cudaFuncSetAttribute(tf32gemm_ca<128, 128, 2, 4, true, false, true>,
                         cudaFuncAttributeMaxDynamicSharedMemorySize, SM_128_NT);
    cudaFuncSetAttribute(tf32gemm_ca<64, 64, 2, 4, true, false, false>,
                         cudaFuncAttributeMaxDynamicSharedMemorySize, SM_64_NT);
    cudaFuncSetAttribute(tf32gemm_ca<128, 128, 2, 4, false, false, true>,
                         cudaFuncAttributeMaxDynamicSharedMemorySize, SM_128_NN);
    cudaFuncSetAttribute(tf32gemm_ca<128, 128, 2, 4, false, true, false>,
                         cudaFuncAttributeMaxDynamicSharedMemorySize, SM_128_NN);

    // 0) pre-convert tf32 operands
    {
        int n4 = BATCH * CDIM * NSP / 4;                     // 4.19M float4
        cvt_tf32_k<<<n4 / 256, 256>>>((const float4*)f_m, (uint4*)cm, n4);
        cvt_tf32_k<<<n4 / 256, 256>>>((const float4*)f_n, (uint4*)cn, n4);
        int w4 = CDIM * CDIM / 4;                            // 65536 float4
        cvt_tf32_k<<<w4 / 256, 256>>>((const float4*)Wkv, (uint4*)cWk, w4);
        cvt_tf32_k<<<w4 / 256, 256>>>((const float4*)Wout, (uint4*)cWout, w4);
    }

    // 1) G[b] = cm[b] @ cn[b]^T   (NT, K=4096), out tf32-rounded
    tf32gemm_ca<128, 128, 2, 4, true, false, true>
        <<<dim3(4, 4, BATCH), 256, SM_128_NT>>>(
        cm, cn, G, nullptr, CDIM, CDIM, NSP,
        CF, 0, CF, 0, CC, 0, 1, 1.0f);

    // 2) T[b,h] = G[b] @ cWk_h^T  (NT, K=512), out fp32
    tf32gemm_ca<64, 64, 2, 4, true, false, false>
        <<<dim3(1, 8, BATCH * NHEADS), 256, SM_64_NT>>>(
        G, cWk, T, nullptr, CDIM, DH, CDIM,
        CC, 0, 0, (long long)DH * CDIM, (long long)NHEADS * THD, THD,
        NHEADS, 1.0f);

    // 3) dots[b,h] = (Wq_h @ T[b,h]) * scale   (NN, K=512) [fp32]
    sgemm<64, 64, 16, 4, 4, false, false, false>
        <<<dim3(1, 1, BATCH * NHEADS), 256>>>(
        Wq, T, dots, nullptr, DH, DH, CDIM,
        0, (long long)DH * CDIM, (long long)NHEADS * THD, THD,
        (long long)NHEADS * DH * DH, (long long)DH * DH,
        NHEADS, 0.125f);

    // 4) attn = softmax(dots)
    softmax64<<<BATCH * NHEADS * DH / 8, 256>>>(dots);

    // 5) U[b] = attn[b,h] @ Wv_h  (NN, K=64) [fp32], out tf32-rounded
    sgemm<64, 64, 16, 4, 4, false, false, true>
        <<<dim3(8, 1, BATCH * NHEADS), 256>>>(
        dots, Wkv + (size_t)CDIM * CDIM, U, nullptr, DH, CDIM, DH,
        (long long)NHEADS * DH * DH, (long long)DH * DH,
        0, (long long)DH * CDIM,
        CC, (long long)DH * CDIM,
        NHEADS, 1.0f);

    // 6) M[b] = cWout @ U[b]   (NN, K=512), out tf32-rounded
    tf32gemm_ca<128, 128, 2, 4, false, false, true>
        <<<dim3(4, 4, BATCH), 256, SM_128_NN>>>(
        cWout, U, Mm, nullptr, CDIM, CDIM, CDIM,
        0, 0, CC, 0, CC, 0, 1, 1.0f);

    // 7) out[b] = M[b] @ cn[b] + bout   (NN, K=512, bias), out fp32
    tf32gemm_ca<128, 128, 2, 4, false, true, false>
        <<<dim3(32, 4, BATCH), 256, SM_128_NN>>>(
        Mm, cn, out, bout, CDIM, NSP, CDIM,
        CC, 0, CF, 0, CF, 0, 1, 1.0f);
}